// round 2
// baseline (speedup 1.0000x reference)
#include <cuda_runtime.h>
#include <cstddef>

// Problem constants (from reference): B=256, L=20, V=9488, S=18
#define BB 256
#define LL 20
#define VV 9488
#define SS 18
#define TLEN (LL - 1)        // 19
#define ROWS_PER_WARP 8      // 32 warps * 8 rows = 256 rows

// Single fused kernel: one block, 32 warps, each warp owns 8 batch rows.
// lane j (0..18) owns padded-target position j, i.e. timestep t = j+1.
__global__ __launch_bounds__(1024, 1)
void scst_fused_kernel(const float* __restrict__ inp,
                       const int*   __restrict__ tgt,
                       const float* __restrict__ reward,
                       const float* __restrict__ reward1,
                       float* __restrict__ out) {
    const int tid  = threadIdx.x;
    const int w    = tid >> 5;     // warp 0..31
    const int lane = tid & 31;

    const bool active = (lane < TLEN);           // TLEN=19 <= SS=18? no: lanes 0..18, SS=18
    // padded target: position j valid from target only for j < S (=18); j=18 is pad -> 0
    const bool has_tgt = active && (lane < SS);

    // 1) Prefetch targets for all 8 rows (independent LDGs -> full MLP)
    int tv[ROWS_PER_WARP];
    #pragma unroll
    for (int r = 0; r < ROWS_PER_WARP; r++) {
        const int b = w * ROWS_PER_WARP + r;
        tv[r] = has_tgt ? tgt[b * SS + lane] : 0;
    }

    // 2) Ballot zero-masks for all 8 rows
    unsigned zb[ROWS_PER_WARP];
    #pragma unroll
    for (int r = 0; r < ROWS_PER_WARP; r++)
        zb[r] = __ballot_sync(0xFFFFFFFFu, active && (tv[r] == 0));

    // 3) Gather kept log-probs (independent LDGs across rows -> MLP ~8/thread)
    const unsigned incl = (2u << lane) - 1u;     // bits 0..lane (lane<=31 ok, lane<=18 used)
    float vs[ROWS_PER_WARP];
    int   cnt = 0;
    #pragma unroll
    for (int r = 0; r < ROWS_PER_WARP; r++) {
        vs[r] = 0.0f;
        if (active && (__popc(zb[r] & incl) <= 1)) {
            const int b = w * ROWS_PER_WARP + r;
            vs[r] = inp[(size_t)b * (size_t)(LL * VV)
                      + (size_t)(lane + 1) * (size_t)VV
                      + (size_t)tv[r]];
            cnt++;
        }
    }
    float val = 0.0f;
    #pragma unroll
    for (int r = 0; r < ROWS_PER_WARP; r++) val += vs[r];

    // 4) Warp reduction
    #pragma unroll
    for (int off = 16; off > 0; off >>= 1) {
        val += __shfl_down_sync(0xFFFFFFFFu, val, off);
        cnt += __shfl_down_sync(0xFFFFFFFFu, cnt, off);
    }

    // 5) Block reduction across 32 warps
    __shared__ float sv[32];
    __shared__ int   sc[32];
    if (lane == 0) { sv[w] = val; sc[w] = cnt; }
    __syncthreads();

    if (w == 0) {
        float v = sv[lane];
        int   c = sc[lane];
        #pragma unroll
        for (int off = 16; off > 0; off >>= 1) {
            v += __shfl_down_sync(0xFFFFFFFFu, v, off);
            c += __shfl_down_sync(0xFFFFFFFFu, c, off);
        }
        if (lane == 0) {
            float rd = reward[0] - reward1[0];
            if (rd < 1.0f) rd = 1.0f;
            out[0] = -(v / (float)c) * rd;
        }
    }
}

extern "C" void kernel_launch(void* const* d_in, const int* in_sizes, int n_in,
                              void* d_out, int out_size) {
    const float* inp     = (const float*)d_in[0];   // [B, L, V] f32
    const int*   tgt     = (const int*)  d_in[1];   // [B, S]    i32
    const float* reward  = (const float*)d_in[2];   // [1]       f32
    const float* reward1 = (const float*)d_in[3];   // [1]       f32
    float*       out     = (float*)d_out;           // [1]       f32

    scst_fused_kernel<<<1, 1024>>>(inp, tgt, reward, reward1, out);
}